// round 15
// baseline (speedup 1.0000x reference)
#include <cuda_runtime.h>
#include <cuda_bf16.h>
#include <cstdint>

#define T_FRAMES 11
#define HID 1024
#define NTOT 1536
#define LN_EPS 1e-5f

// ===================== device scratch =====================
#define MROWS_MAX (8192L * T_FRAMES)          // 90112
__device__ __nv_bfloat16 g_h_hi[MROWS_MAX * HID];
__device__ __nv_bfloat16 g_W_hi[NTOT * HID];
__device__ __nv_bfloat16 g_Wo_h[HID * HID];      // Wo bf16 (row-major)
__device__ __nv_bfloat16 g_WvT[HID * HID];       // Wv^T bf16
__device__ float g_bias[NTOT];
__device__ __nv_bfloat16 g_qk[MROWS_MAX * 512];  // Q|K outputs, bf16
__device__ __nv_bfloat16 g_xb[MROWS_MAX * HID];  // X outputs, bf16

// ===================== PTX helpers (base sm_80+ features only) =====================
__device__ __forceinline__ uint32_t smem_u32(const void* p) {
    uint32_t a;
    asm("{ .reg .u64 t; cvta.to.shared.u64 t, %1; cvt.u32.u64 %0, t; }" : "=r"(a) : "l"(p));
    return a;
}
__device__ __forceinline__ void cp16(uint32_t dst, const void* src) {
    asm volatile("cp.async.cg.shared.global [%0], [%1], 16;" :: "r"(dst), "l"(src));
}
#define CP_COMMIT() asm volatile("cp.async.commit_group;" ::: "memory")
#define CP_WAIT2()  asm volatile("cp.async.wait_group 2;" ::: "memory")

__device__ __forceinline__ void ldsm4(uint32_t& r0, uint32_t& r1, uint32_t& r2, uint32_t& r3,
                                      uint32_t addr) {
    asm volatile("ldmatrix.sync.aligned.m8n8.x4.shared.b16 {%0,%1,%2,%3}, [%4];"
                 : "=r"(r0), "=r"(r1), "=r"(r2), "=r"(r3) : "r"(addr));
}
__device__ __forceinline__ void mma16816(float* c, const uint32_t* a, const uint32_t* b) {
    asm volatile(
        "mma.sync.aligned.m16n8k16.row.col.f32.bf16.bf16.f32 "
        "{%0,%1,%2,%3}, {%4,%5,%6,%7}, {%8,%9}, {%0,%1,%2,%3};"
        : "+f"(c[0]), "+f"(c[1]), "+f"(c[2]), "+f"(c[3])
        : "r"(a[0]), "r"(a[1]), "r"(a[2]), "r"(a[3]), "r"(b[0]), "r"(b[1]));
}

// ===================== prologue: all conversions + transpose + cvec + h->bf16 ======
__global__ __launch_bounds__(256) void prologue_kernel(const float* __restrict__ h,
                                                       const float* __restrict__ Wq,
                                                       const float* __restrict__ Wk,
                                                       const float* __restrict__ bq,
                                                       const float* __restrict__ bk,
                                                       const float* __restrict__ Wo,
                                                       const float* __restrict__ Wv,
                                                       const float* __restrict__ bv,
                                                       const float* __restrict__ bo) {
    const int tid = threadIdx.x;
    const int bx = blockIdx.x;
    if (bx < 1024) {
        int i = bx * 256 + tid;
        float4 v = ((const float4*)Wo)[i];
        union { __nv_bfloat162 b[2]; uint2 u; } ph;
        ph.b[0] = __floats2bfloat162_rn(v.x, v.y);
        ph.b[1] = __floats2bfloat162_rn(v.z, v.w);
        ((uint2*)g_Wo_h)[i] = ph.u;
    } else if (bx < 2048) {
        __shared__ float ts[32][33];
        int t = bx - 1024;
        int tk = t & 31, tc = t >> 5;
        int cx = tid & 31, ky = tid >> 5;
        #pragma unroll
        for (int i = 0; i < 4; i++) {
            int k = ky + i * 8;
            ts[k][cx] = Wv[(size_t)(tk * 32 + k) * HID + tc * 32 + cx];
        }
        __syncthreads();
        #pragma unroll
        for (int i = 0; i < 4; i++) {
            int c = ky + i * 8;
            g_WvT[(size_t)(tc * 32 + c) * HID + tk * 32 + cx] =
                __float2bfloat16(ts[cx][c]);
        }
    } else if (bx < 2560) {
        int i = (bx - 2048) * 256 + tid;
        int row = i >> 8, c4 = i & 255;
        float4 v = (row < 256) ? ((const float4*)(Wq + (size_t)row * HID))[c4]
                               : ((const float4*)(Wk + (size_t)(row - 256) * HID))[c4];
        union { __nv_bfloat162 b[2]; uint2 u; } ph;
        ph.b[0] = __floats2bfloat162_rn(v.x, v.y);
        ph.b[1] = __floats2bfloat162_rn(v.z, v.w);
        ((uint2*)g_W_hi)[i] = ph.u;
        if (i < 128)
            ((float4*)g_bias)[i] = (i < 64) ? ((const float4*)bq)[i] : ((const float4*)bk)[i - 64];
    } else if (bx < 2564) {
        int o = (bx - 2560) * 256 + tid;
        float s = 0.f;
        for (int m = 0; m < HID; m += 4) {
            float4 w = *(const float4*)(Wo + (size_t)o * HID + m);
            float4 b = *(const float4*)(bv + m);
            s = fmaf(w.x,b.x,s); s = fmaf(w.y,b.y,s); s = fmaf(w.z,b.z,s); s = fmaf(w.w,b.w,s);
        }
        g_bias[512 + o] = s + bo[o];
    } else {
        long i = (long)(bx - 2564) * 256 + tid;
        float4 v = ((const float4*)h)[i];
        union { __nv_bfloat162 b[2]; uint2 u; } ph;
        ph.b[0] = __floats2bfloat162_rn(v.x, v.y);
        ph.b[1] = __floats2bfloat162_rn(v.z, v.w);
        ((uint2*)g_h_hi)[i] = ph.u;
    }
}

// ===================== shared GEMM tile machinery =====================
#define BK 64
#define NKS (HID / BK)             // 16
#define MAT_B 16384                // 128 rows x 64 bf16 = 16KB per matrix
#define STAGE_B (2 * MAT_B)        // A|B = 32KB
#define GEMM_SMEM (3 * STAGE_B)    // 96KB

__device__ __forceinline__ uint32_t swz(uint32_t byte) {
    return byte ^ ((byte >> 3) & 0x70);
}

__device__ __forceinline__ void gemm_tile_mainloop(const __nv_bfloat16* __restrict__ A,
                                                   const __nv_bfloat16* __restrict__ B,
                                                   char* sm, uint32_t sb,
                                                   int tid, int wid, int lane,
                                                   int m_w, int n_w,
                                                   float acc[4][4][4]) {
    const int crow = tid >> 3;
    const int ckc  = tid & 7;

    #pragma unroll
    for (int s = 0; s < 3; s++) {
        uint32_t st = sb + s * STAGE_B;
        int ko = s * BK;
        #pragma unroll
        for (int i = 0; i < 4; i++) {
            int row = crow + i * 32;
            uint32_t sw = swz(row * 128 + ckc * 16);
            size_t go = (size_t)row * HID + ko + ckc * 8;
            cp16(st + sw,         A + go);
            cp16(st + MAT_B + sw, B + go);
        }
        CP_COMMIT();
    }

    for (int ks = 0; ks < NKS; ks++) {
        CP_WAIT2();
        __syncthreads();
        const uint32_t st = sb + (ks % 3) * STAGE_B;

        #pragma unroll
        for (int kk = 0; kk < BK / 16; kk++) {
            uint32_t ah[4][4], bh[4][2];
            #pragma unroll
            for (int mt = 0; mt < 4; mt++) {
                uint32_t byte = (uint32_t)(m_w + mt * 16 + (lane & 15)) * 128
                              + kk * 32 + ((lane >> 4) << 4);
                uint32_t sw = swz(byte);
                ldsm4(ah[mt][0], ah[mt][1], ah[mt][2], ah[mt][3], st + sw);
            }
            #pragma unroll
            for (int half = 0; half < 2; half++) {
                int grp = lane >> 3;
                uint32_t rowB = (uint32_t)(n_w + half * 16 + ((grp & 2) << 2) + (lane & 7));
                uint32_t byte = rowB * 128 + kk * 32 + ((grp & 1) << 4);
                uint32_t sw = swz(byte);
                ldsm4(bh[half*2][0], bh[half*2][1], bh[half*2+1][0], bh[half*2+1][1],
                      st + MAT_B + sw);
            }
            #pragma unroll
            for (int mt = 0; mt < 4; mt++)
                #pragma unroll
                for (int nt = 0; nt < 4; nt++)
                    mma16816(acc[mt][nt], ah[mt], bh[nt]);
        }
        __syncthreads();

        if (ks + 3 < NKS) {
            uint32_t st2 = sb + (ks % 3) * STAGE_B;
            int ko = (ks + 3) * BK;
            #pragma unroll
            for (int i = 0; i < 4; i++) {
                int row = crow + i * 32;
                uint32_t sw = swz(row * 128 + ckc * 16);
                size_t go = (size_t)row * HID + ko + ckc * 8;
                cp16(st2 + sw,         A + go);
                cp16(st2 + MAT_B + sw, B + go);
            }
        }
        CP_COMMIT();
    }
}

// ===================== w2 mma: W2 = Wo @ Wv  (bf16, 64 CTAs) =====================
__global__ __launch_bounds__(256, 2) void w2_mma_kernel() {
    extern __shared__ __align__(1024) char sm[];
    const int tid = threadIdx.x, wid = tid >> 5, lane = tid & 31;
    const int m0 = blockIdx.y * 128;
    const int n0 = blockIdx.x * 128;
    const int m_w = (wid & 1) * 64;
    const int n_w = (wid >> 1) * 32;
    const uint32_t sb = smem_u32(sm);

    float acc[4][4][4] = {};
    gemm_tile_mainloop(g_Wo_h + (size_t)m0 * HID, g_WvT + (size_t)n0 * HID,
                       sm, sb, tid, wid, lane, m_w, n_w, acc);

    const int qrow = lane >> 2;
    const int qcol = 2 * (lane & 3);
    #pragma unroll
    for (int nt = 0; nt < 4; nt++) {
        const int col = n0 + n_w + nt * 8 + qcol;
        #pragma unroll
        for (int mt = 0; mt < 4; mt++) {
            int r0 = m0 + m_w + mt * 16 + qrow;
            __nv_bfloat162 v0 = __floats2bfloat162_rn(acc[mt][nt][0], acc[mt][nt][1]);
            __nv_bfloat162 v1 = __floats2bfloat162_rn(acc[mt][nt][2], acc[mt][nt][3]);
            *(__nv_bfloat162*)(g_W_hi + (size_t)(512 + r0) * HID + col)     = v0;
            *(__nv_bfloat162*)(g_W_hi + (size_t)(512 + r0 + 8) * HID + col) = v1;
        }
    }
}

// ===================== main GEMM: [QK|X] = h * W^T + bias =====================
__global__ __launch_bounds__(256, 2) void gemm_kernel() {
    extern __shared__ __align__(1024) char sm[];
    const int tid = threadIdx.x, wid = tid >> 5, lane = tid & 31;
    const long m0 = (long)blockIdx.y * 128;
    const long n0 = (long)blockIdx.x * 128;
    const int m_w = (wid & 1) * 64;
    const int n_w = (wid >> 1) * 32;
    const uint32_t sb = smem_u32(sm);

    float acc[4][4][4] = {};
    gemm_tile_mainloop(g_h_hi + m0 * HID, g_W_hi + n0 * HID,
                       sm, sb, tid, wid, lane, m_w, n_w, acc);

    const int qrow = lane >> 2;
    const int qcol = 2 * (lane & 3);
    if (n0 < 512) {
        #pragma unroll
        for (int nt = 0; nt < 4; nt++) {
            const int col = (int)n0 + n_w + nt * 8 + qcol;
            const float2 bv = *(const float2*)(g_bias + col);
            #pragma unroll
            for (int mt = 0; mt < 4; mt++) {
                long r0 = m0 + m_w + mt * 16 + qrow;
                __nv_bfloat162 v0 = __floats2bfloat162_rn(acc[mt][nt][0] + bv.x,
                                                          acc[mt][nt][1] + bv.y);
                __nv_bfloat162 v1 = __floats2bfloat162_rn(acc[mt][nt][2] + bv.x,
                                                          acc[mt][nt][3] + bv.y);
                *(__nv_bfloat162*)(g_qk + r0 * 512 + col)       = v0;
                *(__nv_bfloat162*)(g_qk + (r0 + 8) * 512 + col) = v1;
            }
        }
    } else {
        #pragma unroll
        for (int nt = 0; nt < 4; nt++) {
            const int colb = (int)n0 + n_w + nt * 8 + qcol;
            const float2 bv = *(const float2*)(g_bias + colb);
            const int col = colb - 512;
            #pragma unroll
            for (int mt = 0; mt < 4; mt++) {
                long r0 = m0 + m_w + mt * 16 + qrow;
                __nv_bfloat162 v0 = __floats2bfloat162_rn(acc[mt][nt][0] + bv.x,
                                                          acc[mt][nt][1] + bv.y);
                __nv_bfloat162 v1 = __floats2bfloat162_rn(acc[mt][nt][2] + bv.x,
                                                          acc[mt][nt][3] + bv.y);
                *(__nv_bfloat162*)(g_xb + r0 * HID + col)       = v0;
                *(__nv_bfloat162*)(g_xb + (r0 + 8) * HID + col) = v1;
            }
        }
    }
}

// ===================== attention + softmax + residual + LN =====================
// x held in registers; no xs smem buffer. smem ~12.5KB, (256,3).
#define QK_STR 520

__global__ __launch_bounds__(256, 3) void attn_kernel(const float* __restrict__ h,
                                                      const float* __restrict__ gamma,
                                                      const float* __restrict__ beta,
                                                      const float* __restrict__ screen_d, int n_screen,
                                                      const float* __restrict__ scale,
                                                      float* __restrict__ out) {
    __shared__ __nv_bfloat16 qk[T_FRAMES * QK_STR];   // 11.2KB
    __shared__ float sc[132];
    __shared__ float redS[8][T_FRAMES];
    __shared__ float redS2[8][T_FRAMES];
    __shared__ float smu[T_FRAMES];
    __shared__ float srs[T_FRAMES];

    const int tid = threadIdx.x;
    const int wid = tid >> 5, lane = tid & 31;
    const long b = blockIdx.x;
    const __nv_bfloat16* __restrict__ qkb = g_qk + b * T_FRAMES * 512;
    const __nv_bfloat16* __restrict__ xb = g_xb + b * T_FRAMES * HID;
    const float* __restrict__ hb = h + b * T_FRAMES * HID;

    for (int idx = tid; idx < T_FRAMES * 64; idx += 256) {
        int r = idx >> 6, c = idx & 63;
        *((uint4*)(qk + r * QK_STR) + c) = ((const uint4*)(qkb + r * 512))[c];
    }
    __syncthreads();

    const float scl = scale[0];
    if (tid < 121) {
        int i = tid / 11, j = tid - i * 11;
        const __nv_bfloat162* q2 = (const __nv_bfloat162*)(qk + i * QK_STR);
        const __nv_bfloat162* k2 = (const __nv_bfloat162*)(qk + j * QK_STR + 256);
        float s = 0.f;
        #pragma unroll 16
        for (int k = 0; k < 128; k++) {
            float2 a = __bfloat1622float2(q2[k]);
            float2 bb = __bfloat1622float2(k2[k]);
            s = fmaf(a.x, bb.x, s);
            s = fmaf(a.y, bb.y, s);
        }
        float r = fabsf((float)(i - j));
        float rr2 = r * r + 1e-6f;
        float wsum = 0.f, sg = 1.f;
        for (int kk = 0; kk < n_screen; kk++) {
            float d = screen_d[kk];
            wsum += sg * rsqrtf(d * d + rr2);
            sg = -sg;
        }
        sc[i * 12 + j] = s * 0.0625f + wsum / (scl + 1e-6f);
    }
    __syncthreads();

    if (tid < T_FRAMES) {
        float* row = sc + tid * 12;
        float m = row[0];
        #pragma unroll
        for (int j = 1; j < 11; j++) m = fmaxf(m, row[j]);
        float sum = 0.f;
        #pragma unroll
        for (int j = 0; j < 11; j++) { float e = expf(row[j] - m); row[j] = e; sum += e; }
        float inv = 1.f / sum;
        #pragma unroll
        for (int j = 0; j < 11; j++) row[j] *= inv;
    }
    __syncthreads();

    // ---- x = h + P@X into registers (vectorized x2) ----
    const __nv_bfloat162* __restrict__ xb2 = (const __nv_bfloat162*)xb;
    const float2* __restrict__ hb2 = (const float2*)hb;
    float2 xr[2][T_FRAMES];
    #pragma unroll
    for (int it = 0; it < 2; it++) {
        int c2 = tid + it * 256;             // pair index 0..511
        float2 xv[11];
        #pragma unroll
        for (int j = 0; j < 11; j++) xv[j] = __bfloat1622float2(xb2[j * 512 + c2]);
        #pragma unroll
        for (int i = 0; i < 11; i++) {
            float ax = 0.f, ay = 0.f;
            #pragma unroll
            for (int j = 0; j < 11; j++) {
                float p = sc[i * 12 + j];
                ax = fmaf(p, xv[j].x, ax);
                ay = fmaf(p, xv[j].y, ay);
            }
            float2 hh = hb2[i * 512 + c2];
            xr[it][i].x = hh.x + ax;
            xr[it][i].y = hh.y + ay;
        }
    }

    // ---- per-row sums from registers -> warp shuffle -> cross-warp smem ----
    #pragma unroll
    for (int i = 0; i < T_FRAMES; i++) {
        float s  = xr[0][i].x + xr[0][i].y + xr[1][i].x + xr[1][i].y;
        float s2 = xr[0][i].x * xr[0][i].x + xr[0][i].y * xr[0][i].y
                 + xr[1][i].x * xr[1][i].x + xr[1][i].y * xr[1][i].y;
        #pragma unroll
        for (int o = 16; o > 0; o >>= 1) {
            s  += __shfl_xor_sync(0xffffffffu, s, o);
            s2 += __shfl_xor_sync(0xffffffffu, s2, o);
        }
        if (lane == 0) { redS[wid][i] = s; redS2[wid][i] = s2; }
    }
    __syncthreads();
    if (tid < T_FRAMES) {
        float ss = 0.f, ss2 = 0.f;
        #pragma unroll
        for (int w = 0; w < 8; w++) { ss += redS[w][tid]; ss2 += redS2[w][tid]; }
        float mu = ss * (1.f / HID);
        float var = ss2 * (1.f / HID) - mu * mu;
        smu[tid] = mu;
        srs[tid] = rsqrtf(var + LN_EPS);
    }
    __syncthreads();

    // ---- normalize from registers, write out ----
    #pragma unroll
    for (int it = 0; it < 2; it++) {
        int c2 = tid + it * 256;
        float2 g = *(const float2*)(gamma + c2 * 2);
        float2 be = *(const float2*)(beta + c2 * 2);
        #pragma unroll
        for (int i = 0; i < 11; i++) {
            float mu = smu[i], rs = srs[i];
            float2 o2;
            o2.x = (xr[it][i].x - mu) * rs * g.x + be.x;
            o2.y = (xr[it][i].y - mu) * rs * g.y + be.y;
            *(float2*)(out + (b * T_FRAMES + i) * HID + c2 * 2) = o2;
        }
    }
}

// ===================== launch =====================
extern "C" void kernel_launch(void* const* d_in, const int* in_sizes, int n_in,
                              void* d_out, int out_size) {
    const float* h        = (const float*)d_in[0];
    const float* Wq       = (const float*)d_in[1];
    const float* bq       = (const float*)d_in[2];
    const float* Wk       = (const float*)d_in[3];
    const float* bk       = (const float*)d_in[4];
    const float* Wv       = (const float*)d_in[5];
    const float* bv       = (const float*)d_in[6];
    const float* Wo       = (const float*)d_in[7];
    const float* bo       = (const float*)d_in[8];
    const float* gamma    = (const float*)d_in[9];
    const float* beta     = (const float*)d_in[10];
    const float* screen_d = (const float*)d_in[11];
    const float* scale    = (const float*)d_in[12];
    const int n_screen = in_sizes[11];
    const long B = in_sizes[0] / (T_FRAMES * HID);
    const long M = B * T_FRAMES;                    // 90112
    float* out = (float*)d_out;

    cudaFuncSetAttribute(gemm_kernel, cudaFuncAttributeMaxDynamicSharedMemorySize, GEMM_SMEM);
    cudaFuncSetAttribute(w2_mma_kernel, cudaFuncAttributeMaxDynamicSharedMemorySize, GEMM_SMEM);

    unsigned conv_blocks = (unsigned)((M * HID / 4) / 256);
    prologue_kernel<<<2564 + conv_blocks, 256>>>(h, Wq, Wk, bq, bk, Wo, Wv, bv, bo);
    w2_mma_kernel<<<dim3(8, 8), 256, GEMM_SMEM>>>();

    dim3 ggrid(NTOT / 128, (unsigned)(M / 128));
    gemm_kernel<<<ggrid, 256, GEMM_SMEM>>>();

    attn_kernel<<<(unsigned)B, 256>>>(h, gamma, beta, screen_d, n_screen, scale, out);
}

// round 16
// speedup vs baseline: 1.1510x; 1.1510x over previous
#include <cuda_runtime.h>
#include <cuda_bf16.h>
#include <cstdint>

#define T_FRAMES 11
#define HID 1024
#define NTOT 1536
#define LN_EPS 1e-5f

// ===================== device scratch =====================
#define MROWS_MAX (8192L * T_FRAMES)          // 90112
__device__ __nv_bfloat16 g_h_hi[MROWS_MAX * HID];
__device__ __nv_bfloat16 g_W_hi[NTOT * HID];
__device__ __nv_bfloat16 g_Wo_h[HID * HID];      // Wo bf16 (row-major)
__device__ __nv_bfloat16 g_WvT[HID * HID];       // Wv^T bf16
__device__ float g_bias[NTOT];
__device__ __nv_bfloat16 g_qk[MROWS_MAX * 512];  // Q|K outputs, bf16
__device__ __nv_bfloat16 g_xb[MROWS_MAX * HID];  // X outputs, bf16

// ===================== PTX helpers (base sm_80+ features only) =====================
__device__ __forceinline__ uint32_t smem_u32(const void* p) {
    uint32_t a;
    asm("{ .reg .u64 t; cvta.to.shared.u64 t, %1; cvt.u32.u64 %0, t; }" : "=r"(a) : "l"(p));
    return a;
}
__device__ __forceinline__ void cp16(uint32_t dst, const void* src) {
    asm volatile("cp.async.cg.shared.global [%0], [%1], 16;" :: "r"(dst), "l"(src));
}
#define CP_COMMIT() asm volatile("cp.async.commit_group;" ::: "memory")
#define CP_WAIT2()  asm volatile("cp.async.wait_group 2;" ::: "memory")

__device__ __forceinline__ void ldsm4(uint32_t& r0, uint32_t& r1, uint32_t& r2, uint32_t& r3,
                                      uint32_t addr) {
    asm volatile("ldmatrix.sync.aligned.m8n8.x4.shared.b16 {%0,%1,%2,%3}, [%4];"
                 : "=r"(r0), "=r"(r1), "=r"(r2), "=r"(r3) : "r"(addr));
}
__device__ __forceinline__ void mma16816(float* c, const uint32_t* a, const uint32_t* b) {
    asm volatile(
        "mma.sync.aligned.m16n8k16.row.col.f32.bf16.bf16.f32 "
        "{%0,%1,%2,%3}, {%4,%5,%6,%7}, {%8,%9}, {%0,%1,%2,%3};"
        : "+f"(c[0]), "+f"(c[1]), "+f"(c[2]), "+f"(c[3])
        : "r"(a[0]), "r"(a[1]), "r"(a[2]), "r"(a[3]), "r"(b[0]), "r"(b[1]));
}

// ===================== prologue: all conversions + transpose + cvec + h->bf16 ======
__global__ __launch_bounds__(256) void prologue_kernel(const float* __restrict__ h,
                                                       const float* __restrict__ Wq,
                                                       const float* __restrict__ Wk,
                                                       const float* __restrict__ bq,
                                                       const float* __restrict__ bk,
                                                       const float* __restrict__ Wo,
                                                       const float* __restrict__ Wv,
                                                       const float* __restrict__ bv,
                                                       const float* __restrict__ bo) {
    const int tid = threadIdx.x;
    const int bx = blockIdx.x;
    if (bx < 1024) {
        int i = bx * 256 + tid;
        float4 v = ((const float4*)Wo)[i];
        union { __nv_bfloat162 b[2]; uint2 u; } ph;
        ph.b[0] = __floats2bfloat162_rn(v.x, v.y);
        ph.b[1] = __floats2bfloat162_rn(v.z, v.w);
        ((uint2*)g_Wo_h)[i] = ph.u;
    } else if (bx < 2048) {
        __shared__ float ts[32][33];
        int t = bx - 1024;
        int tk = t & 31, tc = t >> 5;
        int cx = tid & 31, ky = tid >> 5;
        #pragma unroll
        for (int i = 0; i < 4; i++) {
            int k = ky + i * 8;
            ts[k][cx] = Wv[(size_t)(tk * 32 + k) * HID + tc * 32 + cx];
        }
        __syncthreads();
        #pragma unroll
        for (int i = 0; i < 4; i++) {
            int c = ky + i * 8;
            g_WvT[(size_t)(tc * 32 + c) * HID + tk * 32 + cx] =
                __float2bfloat16(ts[cx][c]);
        }
    } else if (bx < 2560) {
        int i = (bx - 2048) * 256 + tid;
        int row = i >> 8, c4 = i & 255;
        float4 v = (row < 256) ? ((const float4*)(Wq + (size_t)row * HID))[c4]
                               : ((const float4*)(Wk + (size_t)(row - 256) * HID))[c4];
        union { __nv_bfloat162 b[2]; uint2 u; } ph;
        ph.b[0] = __floats2bfloat162_rn(v.x, v.y);
        ph.b[1] = __floats2bfloat162_rn(v.z, v.w);
        ((uint2*)g_W_hi)[i] = ph.u;
        if (i < 128)
            ((float4*)g_bias)[i] = (i < 64) ? ((const float4*)bq)[i] : ((const float4*)bk)[i - 64];
    } else if (bx < 2564) {
        int o = (bx - 2560) * 256 + tid;
        float s = 0.f;
        for (int m = 0; m < HID; m += 4) {
            float4 w = *(const float4*)(Wo + (size_t)o * HID + m);
            float4 b = *(const float4*)(bv + m);
            s = fmaf(w.x,b.x,s); s = fmaf(w.y,b.y,s); s = fmaf(w.z,b.z,s); s = fmaf(w.w,b.w,s);
        }
        g_bias[512 + o] = s + bo[o];
    } else {
        long i = (long)(bx - 2564) * 256 + tid;
        float4 v = ((const float4*)h)[i];
        union { __nv_bfloat162 b[2]; uint2 u; } ph;
        ph.b[0] = __floats2bfloat162_rn(v.x, v.y);
        ph.b[1] = __floats2bfloat162_rn(v.z, v.w);
        ((uint2*)g_h_hi)[i] = ph.u;
    }
}

// ===================== shared GEMM tile machinery =====================
#define BK 64
#define NKS (HID / BK)             // 16
#define MAT_B 16384                // 128 rows x 64 bf16 = 16KB per matrix
#define STAGE_B (2 * MAT_B)        // A|B = 32KB
#define GEMM_SMEM (3 * STAGE_B)    // 96KB

__device__ __forceinline__ uint32_t swz(uint32_t byte) {
    return byte ^ ((byte >> 3) & 0x70);
}

__device__ __forceinline__ void gemm_tile_mainloop(const __nv_bfloat16* __restrict__ A,
                                                   const __nv_bfloat16* __restrict__ B,
                                                   char* sm, uint32_t sb,
                                                   int tid, int wid, int lane,
                                                   int m_w, int n_w,
                                                   float acc[4][4][4]) {
    const int crow = tid >> 3;
    const int ckc  = tid & 7;

    #pragma unroll
    for (int s = 0; s < 3; s++) {
        uint32_t st = sb + s * STAGE_B;
        int ko = s * BK;
        #pragma unroll
        for (int i = 0; i < 4; i++) {
            int row = crow + i * 32;
            uint32_t sw = swz(row * 128 + ckc * 16);
            size_t go = (size_t)row * HID + ko + ckc * 8;
            cp16(st + sw,         A + go);
            cp16(st + MAT_B + sw, B + go);
        }
        CP_COMMIT();
    }

    for (int ks = 0; ks < NKS; ks++) {
        CP_WAIT2();
        __syncthreads();
        const uint32_t st = sb + (ks % 3) * STAGE_B;

        #pragma unroll
        for (int kk = 0; kk < BK / 16; kk++) {
            uint32_t ah[4][4], bh[4][2];
            #pragma unroll
            for (int mt = 0; mt < 4; mt++) {
                uint32_t byte = (uint32_t)(m_w + mt * 16 + (lane & 15)) * 128
                              + kk * 32 + ((lane >> 4) << 4);
                uint32_t sw = swz(byte);
                ldsm4(ah[mt][0], ah[mt][1], ah[mt][2], ah[mt][3], st + sw);
            }
            #pragma unroll
            for (int half = 0; half < 2; half++) {
                int grp = lane >> 3;
                uint32_t rowB = (uint32_t)(n_w + half * 16 + ((grp & 2) << 2) + (lane & 7));
                uint32_t byte = rowB * 128 + kk * 32 + ((grp & 1) << 4);
                uint32_t sw = swz(byte);
                ldsm4(bh[half*2][0], bh[half*2][1], bh[half*2+1][0], bh[half*2+1][1],
                      st + MAT_B + sw);
            }
            #pragma unroll
            for (int mt = 0; mt < 4; mt++)
                #pragma unroll
                for (int nt = 0; nt < 4; nt++)
                    mma16816(acc[mt][nt], ah[mt], bh[nt]);
        }
        __syncthreads();

        if (ks + 3 < NKS) {
            uint32_t st2 = sb + (ks % 3) * STAGE_B;
            int ko = (ks + 3) * BK;
            #pragma unroll
            for (int i = 0; i < 4; i++) {
                int row = crow + i * 32;
                uint32_t sw = swz(row * 128 + ckc * 16);
                size_t go = (size_t)row * HID + ko + ckc * 8;
                cp16(st2 + sw,         A + go);
                cp16(st2 + MAT_B + sw, B + go);
            }
        }
        CP_COMMIT();
    }
}

// ===================== w2 mma: W2 = Wo @ Wv  (bf16, 64 CTAs) =====================
__global__ __launch_bounds__(256, 2) void w2_mma_kernel() {
    extern __shared__ __align__(1024) char sm[];
    const int tid = threadIdx.x, wid = tid >> 5, lane = tid & 31;
    const int m0 = blockIdx.y * 128;
    const int n0 = blockIdx.x * 128;
    const int m_w = (wid & 1) * 64;
    const int n_w = (wid >> 1) * 32;
    const uint32_t sb = smem_u32(sm);

    float acc[4][4][4] = {};
    gemm_tile_mainloop(g_Wo_h + (size_t)m0 * HID, g_WvT + (size_t)n0 * HID,
                       sm, sb, tid, wid, lane, m_w, n_w, acc);

    const int qrow = lane >> 2;
    const int qcol = 2 * (lane & 3);
    #pragma unroll
    for (int nt = 0; nt < 4; nt++) {
        const int col = n0 + n_w + nt * 8 + qcol;
        #pragma unroll
        for (int mt = 0; mt < 4; mt++) {
            int r0 = m0 + m_w + mt * 16 + qrow;
            __nv_bfloat162 v0 = __floats2bfloat162_rn(acc[mt][nt][0], acc[mt][nt][1]);
            __nv_bfloat162 v1 = __floats2bfloat162_rn(acc[mt][nt][2], acc[mt][nt][3]);
            *(__nv_bfloat162*)(g_W_hi + (size_t)(512 + r0) * HID + col)     = v0;
            *(__nv_bfloat162*)(g_W_hi + (size_t)(512 + r0 + 8) * HID + col) = v1;
        }
    }
}

// ===================== main GEMM: [QK|X] = h * W^T + bias =====================
__global__ __launch_bounds__(256, 2) void gemm_kernel() {
    extern __shared__ __align__(1024) char sm[];
    const int tid = threadIdx.x, wid = tid >> 5, lane = tid & 31;
    const long m0 = (long)blockIdx.y * 128;
    const long n0 = (long)blockIdx.x * 128;
    const int m_w = (wid & 1) * 64;
    const int n_w = (wid >> 1) * 32;
    const uint32_t sb = smem_u32(sm);

    float acc[4][4][4] = {};
    gemm_tile_mainloop(g_h_hi + m0 * HID, g_W_hi + n0 * HID,
                       sm, sb, tid, wid, lane, m_w, n_w, acc);

    const int qrow = lane >> 2;
    const int qcol = 2 * (lane & 3);
    if (n0 < 512) {
        #pragma unroll
        for (int nt = 0; nt < 4; nt++) {
            const int col = (int)n0 + n_w + nt * 8 + qcol;
            const float2 bv = *(const float2*)(g_bias + col);
            #pragma unroll
            for (int mt = 0; mt < 4; mt++) {
                long r0 = m0 + m_w + mt * 16 + qrow;
                __nv_bfloat162 v0 = __floats2bfloat162_rn(acc[mt][nt][0] + bv.x,
                                                          acc[mt][nt][1] + bv.y);
                __nv_bfloat162 v1 = __floats2bfloat162_rn(acc[mt][nt][2] + bv.x,
                                                          acc[mt][nt][3] + bv.y);
                *(__nv_bfloat162*)(g_qk + r0 * 512 + col)       = v0;
                *(__nv_bfloat162*)(g_qk + (r0 + 8) * 512 + col) = v1;
            }
        }
    } else {
        #pragma unroll
        for (int nt = 0; nt < 4; nt++) {
            const int colb = (int)n0 + n_w + nt * 8 + qcol;
            const float2 bv = *(const float2*)(g_bias + colb);
            const int col = colb - 512;
            #pragma unroll
            for (int mt = 0; mt < 4; mt++) {
                long r0 = m0 + m_w + mt * 16 + qrow;
                __nv_bfloat162 v0 = __floats2bfloat162_rn(acc[mt][nt][0] + bv.x,
                                                          acc[mt][nt][1] + bv.y);
                __nv_bfloat162 v1 = __floats2bfloat162_rn(acc[mt][nt][2] + bv.x,
                                                          acc[mt][nt][3] + bv.y);
                *(__nv_bfloat162*)(g_xb + r0 * HID + col)       = v0;
                *(__nv_bfloat162*)(g_xb + (r0 + 8) * HID + col) = v1;
            }
        }
    }
}

// ===================== attention + softmax + residual + LN =====================
// x held in registers; no xs smem buffer. (256,2): 128-reg budget -> no spills.
#define QK_STR 520

__global__ __launch_bounds__(256, 2) void attn_kernel(const float* __restrict__ h,
                                                      const float* __restrict__ gamma,
                                                      const float* __restrict__ beta,
                                                      const float* __restrict__ screen_d, int n_screen,
                                                      const float* __restrict__ scale,
                                                      float* __restrict__ out) {
    __shared__ __nv_bfloat16 qk[T_FRAMES * QK_STR];   // 11.2KB
    __shared__ float sc[132];
    __shared__ float redS[8][T_FRAMES];
    __shared__ float redS2[8][T_FRAMES];
    __shared__ float smu[T_FRAMES];
    __shared__ float srs[T_FRAMES];

    const int tid = threadIdx.x;
    const int wid = tid >> 5, lane = tid & 31;
    const long b = blockIdx.x;
    const __nv_bfloat16* __restrict__ qkb = g_qk + b * T_FRAMES * 512;
    const __nv_bfloat16* __restrict__ xb = g_xb + b * T_FRAMES * HID;
    const float* __restrict__ hb = h + b * T_FRAMES * HID;

    for (int idx = tid; idx < T_FRAMES * 64; idx += 256) {
        int r = idx >> 6, c = idx & 63;
        *((uint4*)(qk + r * QK_STR) + c) = ((const uint4*)(qkb + r * 512))[c];
    }
    __syncthreads();

    const float scl = scale[0];
    if (tid < 121) {
        int i = tid / 11, j = tid - i * 11;
        const __nv_bfloat162* q2 = (const __nv_bfloat162*)(qk + i * QK_STR);
        const __nv_bfloat162* k2 = (const __nv_bfloat162*)(qk + j * QK_STR + 256);
        float s = 0.f;
        #pragma unroll 16
        for (int k = 0; k < 128; k++) {
            float2 a = __bfloat1622float2(q2[k]);
            float2 bb = __bfloat1622float2(k2[k]);
            s = fmaf(a.x, bb.x, s);
            s = fmaf(a.y, bb.y, s);
        }
        float r = fabsf((float)(i - j));
        float rr2 = r * r + 1e-6f;
        float wsum = 0.f, sg = 1.f;
        for (int kk = 0; kk < n_screen; kk++) {
            float d = screen_d[kk];
            wsum += sg * rsqrtf(d * d + rr2);
            sg = -sg;
        }
        sc[i * 12 + j] = s * 0.0625f + wsum / (scl + 1e-6f);
    }
    __syncthreads();

    if (tid < T_FRAMES) {
        float* row = sc + tid * 12;
        float m = row[0];
        #pragma unroll
        for (int j = 1; j < 11; j++) m = fmaxf(m, row[j]);
        float sum = 0.f;
        #pragma unroll
        for (int j = 0; j < 11; j++) { float e = expf(row[j] - m); row[j] = e; sum += e; }
        float inv = 1.f / sum;
        #pragma unroll
        for (int j = 0; j < 11; j++) row[j] *= inv;
    }
    __syncthreads();

    // ---- x = h + P@X into registers (vectorized x2) ----
    const __nv_bfloat162* __restrict__ xb2 = (const __nv_bfloat162*)xb;
    const float2* __restrict__ hb2 = (const float2*)hb;
    float2 xr[2][T_FRAMES];
    #pragma unroll
    for (int it = 0; it < 2; it++) {
        int c2 = tid + it * 256;             // pair index 0..511
        float2 xv[11];
        #pragma unroll
        for (int j = 0; j < 11; j++) xv[j] = __bfloat1622float2(xb2[j * 512 + c2]);
        #pragma unroll
        for (int i = 0; i < 11; i++) {
            float ax = 0.f, ay = 0.f;
            #pragma unroll
            for (int j = 0; j < 11; j++) {
                float p = sc[i * 12 + j];
                ax = fmaf(p, xv[j].x, ax);
                ay = fmaf(p, xv[j].y, ay);
            }
            float2 hh = hb2[i * 512 + c2];
            xr[it][i].x = hh.x + ax;
            xr[it][i].y = hh.y + ay;
        }
    }

    // ---- per-row sums from registers -> warp shuffle -> cross-warp smem ----
    #pragma unroll
    for (int i = 0; i < T_FRAMES; i++) {
        float s  = xr[0][i].x + xr[0][i].y + xr[1][i].x + xr[1][i].y;
        float s2 = xr[0][i].x * xr[0][i].x + xr[0][i].y * xr[0][i].y
                 + xr[1][i].x * xr[1][i].x + xr[1][i].y * xr[1][i].y;
        #pragma unroll
        for (int o = 16; o > 0; o >>= 1) {
            s  += __shfl_xor_sync(0xffffffffu, s, o);
            s2 += __shfl_xor_sync(0xffffffffu, s2, o);
        }
        if (lane == 0) { redS[wid][i] = s; redS2[wid][i] = s2; }
    }
    __syncthreads();
    if (tid < T_FRAMES) {
        float ss = 0.f, ss2 = 0.f;
        #pragma unroll
        for (int w = 0; w < 8; w++) { ss += redS[w][tid]; ss2 += redS2[w][tid]; }
        float mu = ss * (1.f / HID);
        float var = ss2 * (1.f / HID) - mu * mu;
        smu[tid] = mu;
        srs[tid] = rsqrtf(var + LN_EPS);
    }
    __syncthreads();

    // ---- normalize from registers, write out ----
    #pragma unroll
    for (int it = 0; it < 2; it++) {
        int c2 = tid + it * 256;
        float2 g = *(const float2*)(gamma + c2 * 2);
        float2 be = *(const float2*)(beta + c2 * 2);
        #pragma unroll
        for (int i = 0; i < 11; i++) {
            float mu = smu[i], rs = srs[i];
            float2 o2;
            o2.x = (xr[it][i].x - mu) * rs * g.x + be.x;
            o2.y = (xr[it][i].y - mu) * rs * g.y + be.y;
            *(float2*)(out + (b * T_FRAMES + i) * HID + c2 * 2) = o2;
        }
    }
}

// ===================== launch =====================
extern "C" void kernel_launch(void* const* d_in, const int* in_sizes, int n_in,
                              void* d_out, int out_size) {
    const float* h        = (const float*)d_in[0];
    const float* Wq       = (const float*)d_in[1];
    const float* bq       = (const float*)d_in[2];
    const float* Wk       = (const float*)d_in[3];
    const float* bk       = (const float*)d_in[4];
    const float* Wv       = (const float*)d_in[5];
    const float* bv       = (const float*)d_in[6];
    const float* Wo       = (const float*)d_in[7];
    const float* bo       = (const float*)d_in[8];
    const float* gamma    = (const float*)d_in[9];
    const float* beta     = (const float*)d_in[10];
    const float* screen_d = (const float*)d_in[11];
    const float* scale    = (const float*)d_in[12];
    const int n_screen = in_sizes[11];
    const long B = in_sizes[0] / (T_FRAMES * HID);
    const long M = B * T_FRAMES;                    // 90112
    float* out = (float*)d_out;

    cudaFuncSetAttribute(gemm_kernel, cudaFuncAttributeMaxDynamicSharedMemorySize, GEMM_SMEM);
    cudaFuncSetAttribute(w2_mma_kernel, cudaFuncAttributeMaxDynamicSharedMemorySize, GEMM_SMEM);

    unsigned conv_blocks = (unsigned)((M * HID / 4) / 256);
    prologue_kernel<<<2564 + conv_blocks, 256>>>(h, Wq, Wk, bq, bk, Wo, Wv, bv, bo);
    w2_mma_kernel<<<dim3(8, 8), 256, GEMM_SMEM>>>();

    dim3 ggrid(NTOT / 128, (unsigned)(M / 128));
    gemm_kernel<<<ggrid, 256, GEMM_SMEM>>>();

    attn_kernel<<<(unsigned)B, 256>>>(h, gamma, beta, screen_d, n_screen, scale, out);
}

// round 17
// speedup vs baseline: 1.1985x; 1.0413x over previous
#include <cuda_runtime.h>
#include <cuda_bf16.h>
#include <cstdint>

#define T_FRAMES 11
#define HID 1024
#define NTOT 1536
#define LN_EPS 1e-5f

// ===================== device scratch =====================
#define MROWS_MAX (8192L * T_FRAMES)          // 90112
__device__ __nv_bfloat16 g_h_hi[MROWS_MAX * HID];
__device__ __nv_bfloat16 g_W_hi[NTOT * HID];
__device__ __nv_bfloat16 g_Wo_h[HID * HID];      // Wo bf16 (row-major)
__device__ __nv_bfloat16 g_WvT[HID * HID];       // Wv^T bf16
__device__ float g_bias[NTOT];
__device__ __nv_bfloat16 g_qk[MROWS_MAX * 512];  // Q|K outputs, bf16
__device__ __nv_bfloat16 g_xb[MROWS_MAX * HID];  // X outputs, bf16

// ===================== PTX helpers (base sm_80+ features only) =====================
__device__ __forceinline__ uint32_t smem_u32(const void* p) {
    uint32_t a;
    asm("{ .reg .u64 t; cvta.to.shared.u64 t, %1; cvt.u32.u64 %0, t; }" : "=r"(a) : "l"(p));
    return a;
}
__device__ __forceinline__ void cp16(uint32_t dst, const void* src) {
    asm volatile("cp.async.cg.shared.global [%0], [%1], 16;" :: "r"(dst), "l"(src));
}
#define CP_COMMIT() asm volatile("cp.async.commit_group;" ::: "memory")
#define CP_WAIT2()  asm volatile("cp.async.wait_group 2;" ::: "memory")

__device__ __forceinline__ void ldsm4(uint32_t& r0, uint32_t& r1, uint32_t& r2, uint32_t& r3,
                                      uint32_t addr) {
    asm volatile("ldmatrix.sync.aligned.m8n8.x4.shared.b16 {%0,%1,%2,%3}, [%4];"
                 : "=r"(r0), "=r"(r1), "=r"(r2), "=r"(r3) : "r"(addr));
}
__device__ __forceinline__ void mma16816(float* c, const uint32_t* a, const uint32_t* b) {
    asm volatile(
        "mma.sync.aligned.m16n8k16.row.col.f32.bf16.bf16.f32 "
        "{%0,%1,%2,%3}, {%4,%5,%6,%7}, {%8,%9}, {%0,%1,%2,%3};"
        : "+f"(c[0]), "+f"(c[1]), "+f"(c[2]), "+f"(c[3])
        : "r"(a[0]), "r"(a[1]), "r"(a[2]), "r"(a[3]), "r"(b[0]), "r"(b[1]));
}

// ===================== prologue: all conversions + transpose + cvec + h->bf16 ======
__global__ __launch_bounds__(256) void prologue_kernel(const float* __restrict__ h,
                                                       const float* __restrict__ Wq,
                                                       const float* __restrict__ Wk,
                                                       const float* __restrict__ bq,
                                                       const float* __restrict__ bk,
                                                       const float* __restrict__ Wo,
                                                       const float* __restrict__ Wv,
                                                       const float* __restrict__ bv,
                                                       const float* __restrict__ bo) {
    const int tid = threadIdx.x;
    const int bx = blockIdx.x;
    if (bx < 1024) {
        int i = bx * 256 + tid;
        float4 v = ((const float4*)Wo)[i];
        union { __nv_bfloat162 b[2]; uint2 u; } ph;
        ph.b[0] = __floats2bfloat162_rn(v.x, v.y);
        ph.b[1] = __floats2bfloat162_rn(v.z, v.w);
        ((uint2*)g_Wo_h)[i] = ph.u;
    } else if (bx < 2048) {
        __shared__ float ts[32][33];
        int t = bx - 1024;
        int tk = t & 31, tc = t >> 5;
        int cx = tid & 31, ky = tid >> 5;
        #pragma unroll
        for (int i = 0; i < 4; i++) {
            int k = ky + i * 8;
            ts[k][cx] = Wv[(size_t)(tk * 32 + k) * HID + tc * 32 + cx];
        }
        __syncthreads();
        #pragma unroll
        for (int i = 0; i < 4; i++) {
            int c = ky + i * 8;
            g_WvT[(size_t)(tc * 32 + c) * HID + tk * 32 + cx] =
                __float2bfloat16(ts[cx][c]);
        }
    } else if (bx < 2560) {
        int i = (bx - 2048) * 256 + tid;
        int row = i >> 8, c4 = i & 255;
        float4 v = (row < 256) ? ((const float4*)(Wq + (size_t)row * HID))[c4]
                               : ((const float4*)(Wk + (size_t)(row - 256) * HID))[c4];
        union { __nv_bfloat162 b[2]; uint2 u; } ph;
        ph.b[0] = __floats2bfloat162_rn(v.x, v.y);
        ph.b[1] = __floats2bfloat162_rn(v.z, v.w);
        ((uint2*)g_W_hi)[i] = ph.u;
        if (i < 128)
            ((float4*)g_bias)[i] = (i < 64) ? ((const float4*)bq)[i] : ((const float4*)bk)[i - 64];
    } else if (bx < 2564) {
        int o = (bx - 2560) * 256 + tid;
        float s = 0.f;
        for (int m = 0; m < HID; m += 4) {
            float4 w = *(const float4*)(Wo + (size_t)o * HID + m);
            float4 b = *(const float4*)(bv + m);
            s = fmaf(w.x,b.x,s); s = fmaf(w.y,b.y,s); s = fmaf(w.z,b.z,s); s = fmaf(w.w,b.w,s);
        }
        g_bias[512 + o] = s + bo[o];
    } else {
        long i = (long)(bx - 2564) * 256 + tid;
        float4 v = ((const float4*)h)[i];
        union { __nv_bfloat162 b[2]; uint2 u; } ph;
        ph.b[0] = __floats2bfloat162_rn(v.x, v.y);
        ph.b[1] = __floats2bfloat162_rn(v.z, v.w);
        ((uint2*)g_h_hi)[i] = ph.u;
    }
}

// ===================== shared GEMM tile machinery =====================
#define BK 64
#define NKS (HID / BK)             // 16
#define MAT_B 16384                // 128 rows x 64 bf16 = 16KB per matrix
#define STAGE_B (2 * MAT_B)        // A|B = 32KB
#define GEMM_SMEM (3 * STAGE_B)    // 96KB

__device__ __forceinline__ uint32_t swz(uint32_t byte) {
    return byte ^ ((byte >> 3) & 0x70);
}

__device__ __forceinline__ void gemm_tile_mainloop(const __nv_bfloat16* __restrict__ A,
                                                   const __nv_bfloat16* __restrict__ B,
                                                   char* sm, uint32_t sb,
                                                   int tid, int wid, int lane,
                                                   int m_w, int n_w,
                                                   float acc[4][4][4]) {
    const int crow = tid >> 3;
    const int ckc  = tid & 7;

    #pragma unroll
    for (int s = 0; s < 3; s++) {
        uint32_t st = sb + s * STAGE_B;
        int ko = s * BK;
        #pragma unroll
        for (int i = 0; i < 4; i++) {
            int row = crow + i * 32;
            uint32_t sw = swz(row * 128 + ckc * 16);
            size_t go = (size_t)row * HID + ko + ckc * 8;
            cp16(st + sw,         A + go);
            cp16(st + MAT_B + sw, B + go);
        }
        CP_COMMIT();
    }

    for (int ks = 0; ks < NKS; ks++) {
        CP_WAIT2();
        __syncthreads();
        const uint32_t st = sb + (ks % 3) * STAGE_B;

        #pragma unroll
        for (int kk = 0; kk < BK / 16; kk++) {
            uint32_t ah[4][4], bh[4][2];
            #pragma unroll
            for (int mt = 0; mt < 4; mt++) {
                uint32_t byte = (uint32_t)(m_w + mt * 16 + (lane & 15)) * 128
                              + kk * 32 + ((lane >> 4) << 4);
                uint32_t sw = swz(byte);
                ldsm4(ah[mt][0], ah[mt][1], ah[mt][2], ah[mt][3], st + sw);
            }
            #pragma unroll
            for (int half = 0; half < 2; half++) {
                int grp = lane >> 3;
                uint32_t rowB = (uint32_t)(n_w + half * 16 + ((grp & 2) << 2) + (lane & 7));
                uint32_t byte = rowB * 128 + kk * 32 + ((grp & 1) << 4);
                uint32_t sw = swz(byte);
                ldsm4(bh[half*2][0], bh[half*2][1], bh[half*2+1][0], bh[half*2+1][1],
                      st + MAT_B + sw);
            }
            #pragma unroll
            for (int mt = 0; mt < 4; mt++)
                #pragma unroll
                for (int nt = 0; nt < 4; nt++)
                    mma16816(acc[mt][nt], ah[mt], bh[nt]);
        }
        __syncthreads();

        if (ks + 3 < NKS) {
            uint32_t st2 = sb + (ks % 3) * STAGE_B;
            int ko = (ks + 3) * BK;
            #pragma unroll
            for (int i = 0; i < 4; i++) {
                int row = crow + i * 32;
                uint32_t sw = swz(row * 128 + ckc * 16);
                size_t go = (size_t)row * HID + ko + ckc * 8;
                cp16(st2 + sw,         A + go);
                cp16(st2 + MAT_B + sw, B + go);
            }
        }
        CP_COMMIT();
    }
}

// ===================== w2 mma: W2 = Wo @ Wv  (bf16, 64 CTAs) =====================
__global__ __launch_bounds__(256, 2) void w2_mma_kernel() {
    extern __shared__ __align__(1024) char sm[];
    const int tid = threadIdx.x, wid = tid >> 5, lane = tid & 31;
    const int m0 = blockIdx.y * 128;
    const int n0 = blockIdx.x * 128;
    const int m_w = (wid & 1) * 64;
    const int n_w = (wid >> 1) * 32;
    const uint32_t sb = smem_u32(sm);

    float acc[4][4][4] = {};
    gemm_tile_mainloop(g_Wo_h + (size_t)m0 * HID, g_WvT + (size_t)n0 * HID,
                       sm, sb, tid, wid, lane, m_w, n_w, acc);

    const int qrow = lane >> 2;
    const int qcol = 2 * (lane & 3);
    #pragma unroll
    for (int nt = 0; nt < 4; nt++) {
        const int col = n0 + n_w + nt * 8 + qcol;
        #pragma unroll
        for (int mt = 0; mt < 4; mt++) {
            int r0 = m0 + m_w + mt * 16 + qrow;
            __nv_bfloat162 v0 = __floats2bfloat162_rn(acc[mt][nt][0], acc[mt][nt][1]);
            __nv_bfloat162 v1 = __floats2bfloat162_rn(acc[mt][nt][2], acc[mt][nt][3]);
            *(__nv_bfloat162*)(g_W_hi + (size_t)(512 + r0) * HID + col)     = v0;
            *(__nv_bfloat162*)(g_W_hi + (size_t)(512 + r0 + 8) * HID + col) = v1;
        }
    }
}

// ===================== main GEMM: [QK|X] = h * W^T + bias =====================
__global__ __launch_bounds__(256, 2) void gemm_kernel() {
    extern __shared__ __align__(1024) char sm[];
    const int tid = threadIdx.x, wid = tid >> 5, lane = tid & 31;
    const long m0 = (long)blockIdx.y * 128;
    const long n0 = (long)blockIdx.x * 128;
    const int m_w = (wid & 1) * 64;
    const int n_w = (wid >> 1) * 32;
    const uint32_t sb = smem_u32(sm);

    float acc[4][4][4] = {};
    gemm_tile_mainloop(g_h_hi + m0 * HID, g_W_hi + n0 * HID,
                       sm, sb, tid, wid, lane, m_w, n_w, acc);

    const int qrow = lane >> 2;
    const int qcol = 2 * (lane & 3);
    if (n0 < 512) {
        #pragma unroll
        for (int nt = 0; nt < 4; nt++) {
            const int col = (int)n0 + n_w + nt * 8 + qcol;
            const float2 bv = *(const float2*)(g_bias + col);
            #pragma unroll
            for (int mt = 0; mt < 4; mt++) {
                long r0 = m0 + m_w + mt * 16 + qrow;
                __nv_bfloat162 v0 = __floats2bfloat162_rn(acc[mt][nt][0] + bv.x,
                                                          acc[mt][nt][1] + bv.y);
                __nv_bfloat162 v1 = __floats2bfloat162_rn(acc[mt][nt][2] + bv.x,
                                                          acc[mt][nt][3] + bv.y);
                *(__nv_bfloat162*)(g_qk + r0 * 512 + col)       = v0;
                *(__nv_bfloat162*)(g_qk + (r0 + 8) * 512 + col) = v1;
            }
        }
    } else {
        #pragma unroll
        for (int nt = 0; nt < 4; nt++) {
            const int colb = (int)n0 + n_w + nt * 8 + qcol;
            const float2 bv = *(const float2*)(g_bias + colb);
            const int col = colb - 512;
            #pragma unroll
            for (int mt = 0; mt < 4; mt++) {
                long r0 = m0 + m_w + mt * 16 + qrow;
                __nv_bfloat162 v0 = __floats2bfloat162_rn(acc[mt][nt][0] + bv.x,
                                                          acc[mt][nt][1] + bv.y);
                __nv_bfloat162 v1 = __floats2bfloat162_rn(acc[mt][nt][2] + bv.x,
                                                          acc[mt][nt][3] + bv.y);
                *(__nv_bfloat162*)(g_xb + r0 * HID + col)       = v0;
                *(__nv_bfloat162*)(g_xb + (r0 + 8) * HID + col) = v1;
            }
        }
    }
}

// ===================== attention + softmax + residual + LN =====================
// Register-LN, j-outer P@X (xv[11] array eliminated -> ~70 regs), (256,3).
#define QK_STR 520

__global__ __launch_bounds__(256, 3) void attn_kernel(const float* __restrict__ h,
                                                      const float* __restrict__ gamma,
                                                      const float* __restrict__ beta,
                                                      const float* __restrict__ screen_d, int n_screen,
                                                      const float* __restrict__ scale,
                                                      float* __restrict__ out) {
    __shared__ __nv_bfloat16 qk[T_FRAMES * QK_STR];   // 11.2KB
    __shared__ float sc[132];
    __shared__ float redS[8][T_FRAMES];
    __shared__ float redS2[8][T_FRAMES];
    __shared__ float smu[T_FRAMES];
    __shared__ float srs[T_FRAMES];

    const int tid = threadIdx.x;
    const int wid = tid >> 5, lane = tid & 31;
    const long b = blockIdx.x;
    const __nv_bfloat16* __restrict__ qkb = g_qk + b * T_FRAMES * 512;
    const __nv_bfloat16* __restrict__ xb = g_xb + b * T_FRAMES * HID;
    const float* __restrict__ hb = h + b * T_FRAMES * HID;

    for (int idx = tid; idx < T_FRAMES * 64; idx += 256) {
        int r = idx >> 6, c = idx & 63;
        *((uint4*)(qk + r * QK_STR) + c) = ((const uint4*)(qkb + r * 512))[c];
    }
    __syncthreads();

    const float scl = scale[0];
    if (tid < 121) {
        int i = tid / 11, j = tid - i * 11;
        const __nv_bfloat162* q2 = (const __nv_bfloat162*)(qk + i * QK_STR);
        const __nv_bfloat162* k2 = (const __nv_bfloat162*)(qk + j * QK_STR + 256);
        float s = 0.f;
        #pragma unroll 16
        for (int k = 0; k < 128; k++) {
            float2 a = __bfloat1622float2(q2[k]);
            float2 bb = __bfloat1622float2(k2[k]);
            s = fmaf(a.x, bb.x, s);
            s = fmaf(a.y, bb.y, s);
        }
        float r = fabsf((float)(i - j));
        float rr2 = r * r + 1e-6f;
        float wsum = 0.f, sg = 1.f;
        for (int kk = 0; kk < n_screen; kk++) {
            float d = screen_d[kk];
            wsum += sg * rsqrtf(d * d + rr2);
            sg = -sg;
        }
        sc[i * 12 + j] = s * 0.0625f + wsum / (scl + 1e-6f);
    }
    __syncthreads();

    if (tid < T_FRAMES) {
        float* row = sc + tid * 12;
        float m = row[0];
        #pragma unroll
        for (int j = 1; j < 11; j++) m = fmaxf(m, row[j]);
        float sum = 0.f;
        #pragma unroll
        for (int j = 0; j < 11; j++) { float e = expf(row[j] - m); row[j] = e; sum += e; }
        float inv = 1.f / sum;
        #pragma unroll
        for (int j = 0; j < 11; j++) row[j] *= inv;
    }
    __syncthreads();

    // ---- x = h + P@X into registers; j-outer to keep xv transient ----
    const __nv_bfloat162* __restrict__ xb2 = (const __nv_bfloat162*)xb;
    const float2* __restrict__ hb2 = (const float2*)hb;
    float2 xr[2][T_FRAMES];
    #pragma unroll
    for (int it = 0; it < 2; it++) {
        int c2 = tid + it * 256;             // pair index 0..511
        float ax[T_FRAMES], ay[T_FRAMES];
        #pragma unroll
        for (int i = 0; i < T_FRAMES; i++) { ax[i] = 0.f; ay[i] = 0.f; }
        #pragma unroll
        for (int j = 0; j < T_FRAMES; j++) {
            float2 xv = __bfloat1622float2(xb2[j * 512 + c2]);
            #pragma unroll
            for (int i = 0; i < T_FRAMES; i++) {
                float p = sc[i * 12 + j];
                ax[i] = fmaf(p, xv.x, ax[i]);
                ay[i] = fmaf(p, xv.y, ay[i]);
            }
        }
        #pragma unroll
        for (int i = 0; i < T_FRAMES; i++) {
            float2 hh = hb2[i * 512 + c2];
            xr[it][i].x = hh.x + ax[i];
            xr[it][i].y = hh.y + ay[i];
        }
    }

    // ---- per-row sums from registers -> warp shuffle -> cross-warp smem ----
    #pragma unroll
    for (int i = 0; i < T_FRAMES; i++) {
        float s  = xr[0][i].x + xr[0][i].y + xr[1][i].x + xr[1][i].y;
        float s2 = xr[0][i].x * xr[0][i].x + xr[0][i].y * xr[0][i].y
                 + xr[1][i].x * xr[1][i].x + xr[1][i].y * xr[1][i].y;
        #pragma unroll
        for (int o = 16; o > 0; o >>= 1) {
            s  += __shfl_xor_sync(0xffffffffu, s, o);
            s2 += __shfl_xor_sync(0xffffffffu, s2, o);
        }
        if (lane == 0) { redS[wid][i] = s; redS2[wid][i] = s2; }
    }
    __syncthreads();
    if (tid < T_FRAMES) {
        float ss = 0.f, ss2 = 0.f;
        #pragma unroll
        for (int w = 0; w < 8; w++) { ss += redS[w][tid]; ss2 += redS2[w][tid]; }
        float mu = ss * (1.f / HID);
        float var = ss2 * (1.f / HID) - mu * mu;
        smu[tid] = mu;
        srs[tid] = rsqrtf(var + LN_EPS);
    }
    __syncthreads();

    // ---- normalize from registers, write out ----
    #pragma unroll
    for (int it = 0; it < 2; it++) {
        int c2 = tid + it * 256;
        float2 g = *(const float2*)(gamma + c2 * 2);
        float2 be = *(const float2*)(beta + c2 * 2);
        #pragma unroll
        for (int i = 0; i < T_FRAMES; i++) {
            float mu = smu[i], rs = srs[i];
            float2 o2;
            o2.x = (xr[it][i].x - mu) * rs * g.x + be.x;
            o2.y = (xr[it][i].y - mu) * rs * g.y + be.y;
            *(float2*)(out + (b * T_FRAMES + i) * HID + c2 * 2) = o2;
        }
    }
}

// ===================== launch =====================
extern "C" void kernel_launch(void* const* d_in, const int* in_sizes, int n_in,
                              void* d_out, int out_size) {
    const float* h        = (const float*)d_in[0];
    const float* Wq       = (const float*)d_in[1];
    const float* bq       = (const float*)d_in[2];
    const float* Wk       = (const float*)d_in[3];
    const float* bk       = (const float*)d_in[4];
    const float* Wv       = (const float*)d_in[5];
    const float* bv       = (const float*)d_in[6];
    const float* Wo       = (const float*)d_in[7];
    const float* bo       = (const float*)d_in[8];
    const float* gamma    = (const float*)d_in[9];
    const float* beta     = (const float*)d_in[10];
    const float* screen_d = (const float*)d_in[11];
    const float* scale    = (const float*)d_in[12];
    const int n_screen = in_sizes[11];
    const long B = in_sizes[0] / (T_FRAMES * HID);
    const long M = B * T_FRAMES;                    // 90112
    float* out = (float*)d_out;

    cudaFuncSetAttribute(gemm_kernel, cudaFuncAttributeMaxDynamicSharedMemorySize, GEMM_SMEM);
    cudaFuncSetAttribute(w2_mma_kernel, cudaFuncAttributeMaxDynamicSharedMemorySize, GEMM_SMEM);

    unsigned conv_blocks = (unsigned)((M * HID / 4) / 256);
    prologue_kernel<<<2564 + conv_blocks, 256>>>(h, Wq, Wk, bq, bk, Wo, Wv, bv, bo);
    w2_mma_kernel<<<dim3(8, 8), 256, GEMM_SMEM>>>();

    dim3 ggrid(NTOT / 128, (unsigned)(M / 128));
    gemm_kernel<<<ggrid, 256, GEMM_SMEM>>>();

    attn_kernel<<<(unsigned)B, 256>>>(h, gamma, beta, screen_d, n_screen, scale, out);
}